// round 12
// baseline (speedup 1.0000x reference)
#include <cuda_runtime.h>
#include <cstdint>
#include <cstddef>

// ---------------------------------------------------------------------------
// Covariance:  cov[b] = (X^T X)/N - mu mu^T, packed upper triangle.
// X: [64, 4096, 256] f32 -> out: [64, 32896] f32
// TF32 mma.sync m16n8k8 SYRK, triangle-only (80 n-units of 64m x 8n / batch,
// 16 verified warp-slots x 5 units).
// KEY CHANGE vs all prior rounds: 4 CTAs/batch x 128 threads (grid 256),
// => 2 CTAs per SM (smem 70.7KB x2 <= 227KB; regs always fit 2x128 thr).
// Two co-resident CTAs have independent barriers, so one CTA's MMA phase
// overlaps the other's LDS/staging phase — breaking the phase-lockstep that
// made every measured chunk time the SERIAL SUM of MMA+LDS+staging.
// Inner loop is the simple proven load-then-mma form.
// ---------------------------------------------------------------------------

static constexpr int BATCH  = 64;
static constexpr int NPTS   = 4096;
static constexpr int DIM    = 256;
static constexpr int TRI    = DIM * (DIM + 1) / 2;   // 32896
static constexpr int KC     = 32;
static constexpr int NCHUNK = NPTS / KC;             // 128
static constexpr int SROW   = 264;                   // 264 % 32 == 8 -> conflict-free
static constexpr int STAGE_F = KC * SROW;            // 8448 floats
// smem: buf[2][STAGE_F] | psum[2*256] | csum[256]
static constexpr int SMEM_FLOATS = 2 * STAGE_F + 2 * 256 + 256;
static constexpr int SMEM_BYTES  = SMEM_FLOATS * 4;  // 70656

// slot tables (verified in R8): slot -> (mA, nA0, cntA, mB, nB0).
// slot s covers units (mA, nA+u) for u<cntA and (mB, nB+u-cntA) for u>=cntA.
__device__ const int8_t SLOT_MA[16] = {0,0,0,0,0,0,0,1, 1,1,1,1,2,2,2,3};
__device__ const int8_t SLOT_NA[16] = {0,5,10,15,20,25,30,11, 16,21,26,31,20,25,30,27};
__device__ const int8_t SLOT_CA[16] = {5,5,5,5,5,5,2,5, 5,5,5,1,5,5,2,5};
__device__ const int8_t SLOT_MB[16] = {0,0,0,0,0,0,1,0, 0,0,0,2,0,0,3,0};
__device__ const int8_t SLOT_NB[16] = {0,0,0,0,0,0,8,0, 0,0,0,16,0,0,24,0};

#define MMA_TF32(ac, A, b0, b1)                                                 \
    asm volatile(                                                               \
        "mma.sync.aligned.m16n8k8.row.col.f32.tf32.tf32.f32 "                   \
        "{%0,%1,%2,%3}, {%4,%5,%6,%7}, {%8,%9}, {%0,%1,%2,%3};"                 \
        : "+f"((ac)[0]), "+f"((ac)[1]), "+f"((ac)[2]), "+f"((ac)[3])            \
        : "r"((A)[0]), "r"((A)[1]), "r"((A)[2]), "r"((A)[3]),                   \
          "r"(b0), "r"(b1))

static __device__ __forceinline__ uint32_t cvt_rna_tf32(float v) {
    uint32_t r;
    asm("cvt.rna.tf32.f32 %0, %1;" : "=r"(r) : "f"(v));
    return r;
}

// one k-step (8 k) over this warp's 5 units: load af once per m-slab,
// bf per unit, 4 MMAs per unit. 26 LDS, 20 MMAs.
static __device__ __forceinline__ void do_ks(
    const uint32_t* __restrict__ cur, int k8,
    int mA64, int cA, int mB64, const int (&nb8)[5],
    float (&acc)[5][4][4], int g, int tig)
{
    const uint32_t* r0p = cur + (k8 + tig) * SROW;
    const uint32_t* r1p = cur + (k8 + tig + 4) * SROW;
    uint32_t af[4][4];
#pragma unroll
    for (int mf = 0; mf < 4; ++mf) {
        const int m0 = mA64 + mf * 16 + g;
        af[mf][0] = r0p[m0];
        af[mf][1] = r0p[m0 + 8];
        af[mf][2] = r1p[m0];
        af[mf][3] = r1p[m0 + 8];
    }
#pragma unroll
    for (int u = 0; u < 5; ++u) {
        if (u < cA) {
            const uint32_t b0 = r0p[nb8[u] + g];
            const uint32_t b1 = r1p[nb8[u] + g];
#pragma unroll
            for (int mf = 0; mf < 4; ++mf)
                MMA_TF32(acc[u][mf], af[mf], b0, b1);
        }
    }
    if (cA < 5) {   // 3 of 16 slots straddle a slab boundary
#pragma unroll
        for (int mf = 0; mf < 4; ++mf) {
            const int m0 = mB64 + mf * 16 + g;
            af[mf][0] = r0p[m0];
            af[mf][1] = r0p[m0 + 8];
            af[mf][2] = r1p[m0];
            af[mf][3] = r1p[m0 + 8];
        }
#pragma unroll
        for (int u = 0; u < 5; ++u) {
            if (u >= cA) {
                const uint32_t b0 = r0p[nb8[u] + g];
                const uint32_t b1 = r1p[nb8[u] + g];
#pragma unroll
                for (int mf = 0; mf < 4; ++mf)
                    MMA_TF32(acc[u][mf], af[mf], b0, b1);
            }
        }
    }
}

__global__ void __launch_bounds__(128, 2)
cov_mma_kernel(const float* __restrict__ X, float* __restrict__ out)
{
    extern __shared__ float sm[];
    float* buf0 = sm;
    float* buf1 = sm + STAGE_F;
    float* psum = sm + 2 * STAGE_F;        // [2][256]
    float* csum = psum + 2 * 256;          // [256]

    const int tid  = threadIdx.x;
    const int lane = tid & 31;
    const int wid  = tid >> 5;             // 0..3
    const int b    = blockIdx.x >> 2;
    const int q    = blockIdx.x & 3;       // quarter
    const int g    = lane >> 2;
    const int tig  = lane & 3;

    // ---- unit assignment: slot = q*4 + wid ----
    const int slot = q * 4 + wid;
    const int mA64 = (int)SLOT_MA[slot] * 64;
    const int cA   = (int)SLOT_CA[slot];
    const int mB64 = (int)SLOT_MB[slot] * 64;
    int nb8[5];
    {
        const int nA = SLOT_NA[slot], nB = SLOT_NB[slot];
#pragma unroll
        for (int u = 0; u < 5; ++u)
            nb8[u] = ((u < cA) ? (nA + u) : (nB + (u - cA))) * 8;
    }

    // staging: 128 threads; thread t owns float4 col (t&63), rows (t>>6)+2j,
    // i.e. chunk-float4 index tid + 128*j, j = 0..15.
    const float4* gp =
        reinterpret_cast<const float4*>(X + (size_t)b * NPTS * DIM) + tid;
    const int dq    = (tid & 63) * 4;
    const int krow0 = tid >> 6;            // 0..1

    float acc[5][4][4] = {};
    float s4[4] = {0.f, 0.f, 0.f, 0.f};
    float4 v[8];

#define STAGE_GROUP(dst, j) do {                                                \
        uint32_t r0 = cvt_rna_tf32(v[(j) & 7].x), r1 = cvt_rna_tf32(v[(j) & 7].y); \
        uint32_t r2 = cvt_rna_tf32(v[(j) & 7].z), r3 = cvt_rna_tf32(v[(j) & 7].w); \
        s4[0] += __uint_as_float(r0); s4[1] += __uint_as_float(r1);             \
        s4[2] += __uint_as_float(r2); s4[3] += __uint_as_float(r3);             \
        *reinterpret_cast<float4*>(&(dst)[(krow0 + 2 * (j)) * SROW + dq]) =     \
            make_float4(__uint_as_float(r0), __uint_as_float(r1),               \
                        __uint_as_float(r2), __uint_as_float(r3));              \
    } while (0)

    // ---- prologue: stage chunk 0 ----
#pragma unroll
    for (int half = 0; half < 2; ++half) {
#pragma unroll
        for (int j = 0; j < 8; ++j) v[j] = gp[(half * 8 + j) * 128];
#pragma unroll
        for (int j = 0; j < 8; ++j) STAGE_GROUP(buf0, half * 8 + j);
    }
    __syncthreads();

#pragma unroll 1
    for (int c = 0; c < NCHUNK; ++c) {
        const bool more = (c + 1 < NCHUNK);
        const uint32_t* cur =
            reinterpret_cast<const uint32_t*>((c & 1) ? buf1 : buf0);
        float* nxt = (c & 1) ? buf0 : buf1;

        if (more) {                     // LDG batch A for chunk c+1 (j 0..7)
#pragma unroll
            for (int j = 0; j < 8; ++j)
                v[j] = gp[(c + 1) * 2048 + j * 128];
        }

        do_ks(cur,  0, mA64, cA, mB64, nb8, acc, g, tig);
        do_ks(cur,  8, mA64, cA, mB64, nb8, acc, g, tig);

        if (more) {
#pragma unroll
            for (int j = 0; j < 8; ++j) STAGE_GROUP(nxt, j);
#pragma unroll
            for (int j = 0; j < 8; ++j)   // LDG batch B (j 8..15)
                v[j] = gp[(c + 1) * 2048 + (8 + j) * 128];
        }

        do_ks(cur, 16, mA64, cA, mB64, nb8, acc, g, tig);
        do_ks(cur, 24, mA64, cA, mB64, nb8, acc, g, tig);

        if (more) {
#pragma unroll
            for (int j = 0; j < 8; ++j) STAGE_GROUP(nxt, 8 + j);
        }
        __syncthreads();
    }

    // ---- column-sum reduction ----
    psum[krow0 * 256 + dq + 0] = s4[0];
    psum[krow0 * 256 + dq + 1] = s4[1];
    psum[krow0 * 256 + dq + 2] = s4[2];
    psum[krow0 * 256 + dq + 3] = s4[3];
    __syncthreads();
    csum[tid]       = psum[tid]       + psum[256 + tid];
    csum[tid + 128] = psum[tid + 128] + psum[256 + tid + 128];
    __syncthreads();

    // ---- epilogue: cov = acc/N - mu_d mu_e, packed upper triangle ----
    const float invN = 1.0f / (float)NPTS;
    const size_t outb = (size_t)b * TRI;

#pragma unroll
    for (int u = 0; u < 5; ++u) {
        const int mb = (u < cA) ? mA64 : mB64;
#pragma unroll
        for (int mf = 0; mf < 4; ++mf) {
#pragma unroll
            for (int cc = 0; cc < 4; ++cc) {
                const int d = mb + mf * 16 + g + (cc >> 1) * 8;
                const int e = nb8[u] + 2 * tig + (cc & 1);
                if (e >= d) {
                    const float mu_d = csum[d] * invN;
                    const float mu_e = csum[e] * invN;
                    const int idx = d * DIM - (d * (d - 1)) / 2 - d + e;
                    out[outb + (size_t)idx] = acc[u][mf][cc] * invN - mu_d * mu_e;
                }
            }
        }
    }
}

extern "C" void kernel_launch(void* const* d_in, const int* in_sizes, int n_in,
                              void* d_out, int out_size)
{
    const float* X = (const float*)d_in[0];
    float* out = (float*)d_out;
    cudaFuncSetAttribute(cov_mma_kernel,
                         cudaFuncAttributeMaxDynamicSharedMemorySize,
                         SMEM_BYTES);
    cov_mma_kernel<<<BATCH * 4, 128, SMEM_BYTES>>>(X, out);
}

// round 13
// speedup vs baseline: 1.5371x; 1.5371x over previous
#include <cuda_runtime.h>
#include <cstdint>
#include <cstddef>

// ---------------------------------------------------------------------------
// Covariance:  cov[b] = (X^T X)/N - mu mu^T, packed upper triangle.
// X: [64, 4096, 256] f32 -> out: [64, 32896] f32
// FP16 mma.sync m16n8k16 SYRK (f32 accum), triangle-only (verified 16-slot
// tables, 5 units of 64m x 8n per warp). 2 CTAs/batch, 256 thr, KC=32.
// f16 halves MMA count, LDS bytes, STS bytes, and cvt count vs TF32 —
// shrinking every term of the (measured, stubbornly serial) chunk sum.
// SMEM tile: k-pair packed [kp=16][256 d] f16x2 cells, word stride 264
// (== 8 mod 32 banks -> conflict-free fragment LDS and STS.128).
// f16 RN has the same 11-bit significand as TF32 -> rel_err unchanged.
// ---------------------------------------------------------------------------

static constexpr int BATCH  = 64;
static constexpr int NPTS   = 4096;
static constexpr int DIM    = 256;
static constexpr int TRI    = DIM * (DIM + 1) / 2;   // 32896
static constexpr int KC     = 32;                    // k per chunk (16 kp rows)
static constexpr int NCHUNK = NPTS / KC;             // 128
static constexpr int SROWW  = 264;                   // u32 words per kp row
static constexpr int STAGE_W = 16 * SROWW;           // 4224 words per buffer
// smem (u32 words): buf[2][STAGE_W] | psum[4*256] | csum[256]
static constexpr int SMEM_WORDS = 2 * STAGE_W + 4 * 256 + 256;
static constexpr int SMEM_BYTES = SMEM_WORDS * 4;    // 38912

// slot tables (verified R8): slot -> (mA, nA0, cntA, mB, nB0).
__device__ const int8_t SLOT_MA[16] = {0,0,0,0,0,0,0,1, 1,1,1,1,2,2,2,3};
__device__ const int8_t SLOT_NA[16] = {0,5,10,15,20,25,30,11, 16,21,26,31,20,25,30,27};
__device__ const int8_t SLOT_CA[16] = {5,5,5,5,5,5,2,5, 5,5,5,1,5,5,2,5};
__device__ const int8_t SLOT_MB[16] = {0,0,0,0,0,0,1,0, 0,0,0,2,0,0,3,0};
__device__ const int8_t SLOT_NB[16] = {0,0,0,0,0,0,8,0, 0,0,0,16,0,0,24,0};
// boundary slots (6,14,11) on distinct SMSPs.
__device__ const int8_t SLOT_OF[2][8] = {
    {0, 6, 2, 4, 8, 10, 12, 14},
    {1, 3, 5, 7, 9, 11, 13, 15}};

#define MMA_F16(ac, A, b0, b1)                                                  \
    asm volatile(                                                               \
        "mma.sync.aligned.m16n8k16.row.col.f32.f16.f16.f32 "                    \
        "{%0,%1,%2,%3}, {%4,%5,%6,%7}, {%8,%9}, {%0,%1,%2,%3};"                 \
        : "+f"((ac)[0]), "+f"((ac)[1]), "+f"((ac)[2]), "+f"((ac)[3])            \
        : "r"((A)[0]), "r"((A)[1]), "r"((A)[2]), "r"((A)[3]),                   \
          "r"(b0), "r"(b1))

// pack {lo = lo_f, hi = hi_f} as f16x2 (PTX: cvt d,a,b -> d = {lo=b, hi=a})
static __device__ __forceinline__ uint32_t pack_f16x2(float hi_f, float lo_f) {
    uint32_t r;
    asm("cvt.rn.f16x2.f32 %0, %1, %2;" : "=r"(r) : "f"(hi_f), "f"(lo_f));
    return r;
}

// one k16 step over this warp's 5 units.
// A frag: a0=cell(tig, m+g) a1=cell(tig, m+g+8) a2=cell(tig+4, m+g) a3=(+8)
// B frag: b0=cell(tig, n+g) b1=cell(tig+4, n+g)     [cell rows offset by ks8]
static __device__ __forceinline__ void do_ks(
    const uint32_t* __restrict__ cur, int ks8,
    int mA64, int cA, int mB64, const int (&nb8)[5],
    float (&acc)[5][4][4], int g, int tig)
{
    const uint32_t* r0p = cur + (ks8 + tig) * SROWW;
    const uint32_t* r1p = cur + (ks8 + tig + 4) * SROWW;
    uint32_t af[4][4];
#pragma unroll
    for (int mf = 0; mf < 4; ++mf) {
        const int m0 = mA64 + mf * 16 + g;
        af[mf][0] = r0p[m0];
        af[mf][1] = r0p[m0 + 8];
        af[mf][2] = r1p[m0];
        af[mf][3] = r1p[m0 + 8];
    }
#pragma unroll
    for (int u = 0; u < 5; ++u) {
        if (u < cA) {
            const uint32_t b0 = r0p[nb8[u] + g];
            const uint32_t b1 = r1p[nb8[u] + g];
#pragma unroll
            for (int mf = 0; mf < 4; ++mf)
                MMA_F16(acc[u][mf], af[mf], b0, b1);
        }
    }
    if (cA < 5) {   // 3 of 16 slots straddle a slab boundary
#pragma unroll
        for (int mf = 0; mf < 4; ++mf) {
            const int m0 = mB64 + mf * 16 + g;
            af[mf][0] = r0p[m0];
            af[mf][1] = r0p[m0 + 8];
            af[mf][2] = r1p[m0];
            af[mf][3] = r1p[m0 + 8];
        }
#pragma unroll
        for (int u = 0; u < 5; ++u) {
            if (u >= cA) {
                const uint32_t b0 = r0p[nb8[u] + g];
                const uint32_t b1 = r1p[nb8[u] + g];
#pragma unroll
                for (int mf = 0; mf < 4; ++mf)
                    MMA_F16(acc[u][mf], af[mf], b0, b1);
            }
        }
    }
}

__global__ void __launch_bounds__(256, 1)
cov_mma_kernel(const float* __restrict__ X, float* __restrict__ out)
{
    extern __shared__ uint32_t smw[];
    uint32_t* buf0 = smw;
    uint32_t* buf1 = smw + STAGE_W;
    float* psum = reinterpret_cast<float*>(smw + 2 * STAGE_W);   // [4][256]
    float* csum = psum + 4 * 256;                                // [256]

    const int tid  = threadIdx.x;
    const int lane = tid & 31;
    const int wid  = tid >> 5;
    const int b    = blockIdx.x >> 1;
    const int h    = blockIdx.x & 1;
    const int g    = lane >> 2;
    const int tig  = lane & 3;

    // ---- unit assignment ----
    const int slot = SLOT_OF[h][wid];
    const int mA64 = (int)SLOT_MA[slot] * 64;
    const int cA   = (int)SLOT_CA[slot];
    const int mB64 = (int)SLOT_MB[slot] * 64;
    int nb8[5];
    {
        const int nA = SLOT_NA[slot], nB = SLOT_NB[slot];
#pragma unroll
        for (int u = 0; u < 5; ++u)
            nb8[u] = ((u < cA) ? (nA + u) : (nB + (u - cA))) * 8;
    }

    // staging: thread t owns d-quad (t&63)*4; kp rows (t>>6) + 4j, j=0..3.
    const float4* gp =
        reinterpret_cast<const float4*>(X + (size_t)b * NPTS * DIM);
    const int q64   = tid & 63;            // float4 index within a row
    const int dq4   = q64 * 4;             // word col in stage tile
    const int krow0 = tid >> 6;            // 0..3

    float acc[5][4][4] = {};
    float s4[4] = {0.f, 0.f, 0.f, 0.f};
    float4 va[2], vb[2];

    // stage one j-group: rows n0 = base + 2*kp, n0+1 -> packed cell row kp
#define STAGE_J(dst, j, A, B) do {                                              \
        const int kp = krow0 + 4 * (j);                                         \
        uint32_t p0 = pack_f16x2((B).x, (A).x);                                 \
        uint32_t p1 = pack_f16x2((B).y, (A).y);                                 \
        uint32_t p2 = pack_f16x2((B).z, (A).z);                                 \
        uint32_t p3 = pack_f16x2((B).w, (A).w);                                 \
        s4[0] += (A).x + (B).x;  s4[1] += (A).y + (B).y;                        \
        s4[2] += (A).z + (B).z;  s4[3] += (A).w + (B).w;                        \
        asm volatile("st.shared.v4.b32 [%0], {%1, %2, %3, %4};"                 \
            :: "l"(&(dst)[kp * SROWW + dq4]),                                   \
               "r"(p0), "r"(p1), "r"(p2), "r"(p3) : "memory");                  \
    } while (0)

#define LDG_J(c1, j, slot2) do {                                                \
        const int n0 = (c1) * KC + 2 * (krow0 + 4 * (j));                       \
        va[slot2] = gp[(size_t)n0 * 64 + q64];                                  \
        vb[slot2] = gp[(size_t)(n0 + 1) * 64 + q64];                            \
    } while (0)

    // ---- prologue: stage chunk 0 ----
#pragma unroll
    for (int jj = 0; jj < 2; ++jj) {
        LDG_J(0, 2 * jj + 0, 0);
        LDG_J(0, 2 * jj + 1, 1);
        STAGE_J(buf0, 2 * jj + 0, va[0], vb[0]);
        STAGE_J(buf0, 2 * jj + 1, va[1], vb[1]);
    }
    __syncthreads();

#pragma unroll 1
    for (int c = 0; c < NCHUNK; ++c) {
        const bool more = (c + 1 < NCHUNK);
        const uint32_t* cur = (c & 1) ? buf1 : buf0;
        uint32_t* nxt = (c & 1) ? buf0 : buf1;

        if (more) { LDG_J(c + 1, 0, 0); LDG_J(c + 1, 1, 1); }

        do_ks(cur, 0, mA64, cA, mB64, nb8, acc, g, tig);   // k 0..15

        if (more) {
            STAGE_J(nxt, 0, va[0], vb[0]);
            STAGE_J(nxt, 1, va[1], vb[1]);
            LDG_J(c + 1, 2, 0); LDG_J(c + 1, 3, 1);
        }

        do_ks(cur, 8, mA64, cA, mB64, nb8, acc, g, tig);   // k 16..31

        if (more) {
            STAGE_J(nxt, 2, va[0], vb[0]);
            STAGE_J(nxt, 3, va[1], vb[1]);
        }
        __syncthreads();
    }

    // ---- column-sum reduction ----
    psum[krow0 * 256 + dq4 + 0] = s4[0];
    psum[krow0 * 256 + dq4 + 1] = s4[1];
    psum[krow0 * 256 + dq4 + 2] = s4[2];
    psum[krow0 * 256 + dq4 + 3] = s4[3];
    __syncthreads();
    csum[tid] = psum[tid] + psum[256 + tid] + psum[512 + tid] + psum[768 + tid];
    __syncthreads();

    // ---- epilogue: cov = acc/N - mu_d mu_e, packed upper triangle ----
    const float invN = 1.0f / (float)NPTS;
    const size_t outb = (size_t)b * TRI;

#pragma unroll
    for (int u = 0; u < 5; ++u) {
        const int mb = (u < cA) ? mA64 : mB64;
#pragma unroll
        for (int mf = 0; mf < 4; ++mf) {
#pragma unroll
            for (int cc = 0; cc < 4; ++cc) {
                const int d = mb + mf * 16 + g + (cc >> 1) * 8;
                const int e = nb8[u] + 2 * tig + (cc & 1);
                if (e >= d) {
                    const float mu_d = csum[d] * invN;
                    const float mu_e = csum[e] * invN;
                    const int idx = d * DIM - (d * (d - 1)) / 2 - d + e;
                    out[outb + (size_t)idx] = acc[u][mf][cc] * invN - mu_d * mu_e;
                }
            }
        }
    }
}

extern "C" void kernel_launch(void* const* d_in, const int* in_sizes, int n_in,
                              void* d_out, int out_size)
{
    const float* X = (const float*)d_in[0];
    float* out = (float*)d_out;
    cudaFuncSetAttribute(cov_mma_kernel,
                         cudaFuncAttributeMaxDynamicSharedMemorySize,
                         SMEM_BYTES);
    cov_mma_kernel<<<BATCH * 2, 256, SMEM_BYTES>>>(X, out);
}

// round 17
// speedup vs baseline: 1.6830x; 1.0949x over previous
#include <cuda_runtime.h>
#include <cstdint>
#include <cstddef>

// ---------------------------------------------------------------------------
// Covariance:  cov[b] = (X^T X)/N - mu mu^T, packed upper triangle.
// X: [64, 4096, 256] f32 -> out: [64, 32896] f32
// FP16 mma.sync m16n8k16 SYRK (f32 accum), triangle-only (verified 16-slot
// tables, 5 units of 64m x 8n per warp). 2 CTAs/batch, 256 thr, KC=32.
// cp.async ring of 3 f32 chunk buffers, prefetch distance 2.
// R15 RACE FIX: cp.async wait_group is PER-THREAD, so each thread now issues
// exactly the float4s its own CONVERT reads (indices 128*krow0+q64+512j and
// +64). No cross-thread cp.async dependency remains; all other edges are
// ordered by the per-chunk __syncthreads.
// ---------------------------------------------------------------------------

static constexpr int BATCH  = 64;
static constexpr int NPTS   = 4096;
static constexpr int DIM    = 256;
static constexpr int TRI    = DIM * (DIM + 1) / 2;   // 32896
static constexpr int KC     = 32;                    // k per chunk (16 kp rows)
static constexpr int NCHUNK = NPTS / KC;             // 128
static constexpr int SROWW  = 264;                   // u32 words per kp row (f16 tile)
static constexpr int CHUNK_BYTES = KC * DIM * 4;     // 32768 (contiguous in gmem)

// smem byte layout
static constexpr int FB0   = 0;                       // 3 x 32768 f32 ring
static constexpr int HT0   = 3 * CHUNK_BYTES;         // 2 x 16896 f16 tiles
static constexpr int HTSZ  = 16 * SROWW * 4;          // 16896
static constexpr int PSUM  = HT0 + 2 * HTSZ;          // 4*256 f32
static constexpr int CSUM  = PSUM + 4 * 256 * 4;      // 256 f32
static constexpr int SMEM_BYTES = CSUM + 256 * 4;     // 137216

// slot tables (verified R8): slot -> (mA, nA0, cntA, mB, nB0).
__device__ const int8_t SLOT_MA[16] = {0,0,0,0,0,0,0,1, 1,1,1,1,2,2,2,3};
__device__ const int8_t SLOT_NA[16] = {0,5,10,15,20,25,30,11, 16,21,26,31,20,25,30,27};
__device__ const int8_t SLOT_CA[16] = {5,5,5,5,5,5,2,5, 5,5,5,1,5,5,2,5};
__device__ const int8_t SLOT_MB[16] = {0,0,0,0,0,0,1,0, 0,0,0,2,0,0,3,0};
__device__ const int8_t SLOT_NB[16] = {0,0,0,0,0,0,8,0, 0,0,0,16,0,0,24,0};
__device__ const int8_t SLOT_OF[2][8] = {
    {0, 6, 2, 4, 8, 10, 12, 14},
    {1, 3, 5, 7, 9, 11, 13, 15}};

#define MMA_F16(ac, A, b0, b1)                                                  \
    asm volatile(                                                               \
        "mma.sync.aligned.m16n8k16.row.col.f32.f16.f16.f32 "                    \
        "{%0,%1,%2,%3}, {%4,%5,%6,%7}, {%8,%9}, {%0,%1,%2,%3};"                 \
        : "+f"((ac)[0]), "+f"((ac)[1]), "+f"((ac)[2]), "+f"((ac)[3])            \
        : "r"((A)[0]), "r"((A)[1]), "r"((A)[2]), "r"((A)[3]),                   \
          "r"(b0), "r"(b1))

static __device__ __forceinline__ uint32_t pack_f16x2(float hi_f, float lo_f) {
    uint32_t r;
    asm("cvt.rn.f16x2.f32 %0, %1, %2;" : "=r"(r) : "f"(hi_f), "f"(lo_f));
    return r;
}

#define CP_ASYNC16(saddr, gptr)                                                 \
    asm volatile("cp.async.cg.shared.global [%0], [%1], 16;"                    \
                 :: "r"(saddr), "l"(gptr) : "memory")
#define CP_COMMIT()  asm volatile("cp.async.commit_group;" ::: "memory")
#define CP_WAIT2()   asm volatile("cp.async.wait_group 2;" ::: "memory")

// one k16 step over this warp's 5 units (same fragment layout as R13).
static __device__ __forceinline__ void do_ks(
    const uint32_t* __restrict__ cur, int ks8,
    int mA64, int cA, int mB64, const int (&nb8)[5],
    float (&acc)[5][4][4], int g, int tig)
{
    const uint32_t* r0p = cur + (ks8 + tig) * SROWW;
    const uint32_t* r1p = cur + (ks8 + tig + 4) * SROWW;
    uint32_t af[4][4];
#pragma unroll
    for (int mf = 0; mf < 4; ++mf) {
        const int m0 = mA64 + mf * 16 + g;
        af[mf][0] = r0p[m0];
        af[mf][1] = r0p[m0 + 8];
        af[mf][2] = r1p[m0];
        af[mf][3] = r1p[m0 + 8];
    }
#pragma unroll
    for (int u = 0; u < 5; ++u) {
        if (u < cA) {
            const uint32_t b0 = r0p[nb8[u] + g];
            const uint32_t b1 = r1p[nb8[u] + g];
#pragma unroll
            for (int mf = 0; mf < 4; ++mf)
                MMA_F16(acc[u][mf], af[mf], b0, b1);
        }
    }
    if (cA < 5) {
#pragma unroll
        for (int mf = 0; mf < 4; ++mf) {
            const int m0 = mB64 + mf * 16 + g;
            af[mf][0] = r0p[m0];
            af[mf][1] = r0p[m0 + 8];
            af[mf][2] = r1p[m0];
            af[mf][3] = r1p[m0 + 8];
        }
#pragma unroll
        for (int u = 0; u < 5; ++u) {
            if (u >= cA) {
                const uint32_t b0 = r0p[nb8[u] + g];
                const uint32_t b1 = r1p[nb8[u] + g];
#pragma unroll
                for (int mf = 0; mf < 4; ++mf)
                    MMA_F16(acc[u][mf], af[mf], b0, b1);
            }
        }
    }
}

__global__ void __launch_bounds__(256, 1)
cov_mma_kernel(const float* __restrict__ X, float* __restrict__ out)
{
    extern __shared__ char smem[];
    float* psum = reinterpret_cast<float*>(smem + PSUM);   // [4][256]
    float* csum = reinterpret_cast<float*>(smem + CSUM);   // [256]

    const int tid  = threadIdx.x;
    const int lane = tid & 31;
    const int wid  = tid >> 5;
    const int b    = blockIdx.x >> 1;
    const int h    = blockIdx.x & 1;
    const int g    = lane >> 2;
    const int tig  = lane & 3;

    uint32_t smem_u32;
    asm("{ .reg .u64 t; cvta.to.shared.u64 t, %1; cvt.u32.u64 %0, t; }"
        : "=r"(smem_u32) : "l"(smem));

    // ---- unit assignment ----
    const int slot = SLOT_OF[h][wid];
    const int mA64 = (int)SLOT_MA[slot] * 64;
    const int cA   = (int)SLOT_CA[slot];
    const int mB64 = (int)SLOT_MB[slot] * 64;
    int nb8[5];
    {
        const int nA = SLOT_NA[slot], nB = SLOT_NB[slot];
#pragma unroll
        for (int u = 0; u < 5; ++u)
            nb8[u] = ((u < cA) ? (nA + u) : (nB + (u - cA))) * 8;
    }

    const char* gbase = reinterpret_cast<const char*>(X) +
                        (size_t)b * NPTS * DIM * 4;
    const int q64   = tid & 63;            // float4 col index within a row
    const int dq4   = q64 * 4;             // word col in f16 tile
    const int krow0 = tid >> 6;            // 0..3

    // self-consistent cp.async base: thread t copies float4 indices
    // {128*krow0 + q64 + 512j, +64} — exactly what its CONVERT reads.
    const uint32_t toff = (uint32_t)(128 * krow0 + q64) * 16u;

    float acc[5][4][4] = {};
    float s4[4] = {0.f, 0.f, 0.f, 0.f};

#define ISSUE_CHUNK(c) do {                                                     \
        const uint32_t sb = smem_u32 + FB0 + ((c) % 3) * CHUNK_BYTES + toff;    \
        const char* gb = gbase + (size_t)(c) * CHUNK_BYTES + toff;              \
        CP_ASYNC16(sb + 0 * 8192u,         gb + 0 * 8192);                      \
        CP_ASYNC16(sb + 0 * 8192u + 1024u, gb + 0 * 8192 + 1024);               \
        CP_ASYNC16(sb + 1 * 8192u,         gb + 1 * 8192);                      \
        CP_ASYNC16(sb + 1 * 8192u + 1024u, gb + 1 * 8192 + 1024);               \
        CP_ASYNC16(sb + 2 * 8192u,         gb + 2 * 8192);                      \
        CP_ASYNC16(sb + 2 * 8192u + 1024u, gb + 2 * 8192 + 1024);               \
        CP_ASYNC16(sb + 3 * 8192u,         gb + 3 * 8192);                      \
        CP_ASYNC16(sb + 3 * 8192u + 1024u, gb + 3 * 8192 + 1024);               \
    } while (0)

    // convert f32 ring slot (chunk c) -> f16 tile ht[(c)&1], accumulate s4.
    // Reads ONLY float4s this thread itself cp.async'd (per-thread wait OK).
#define CONVERT_CHUNK(c) do {                                                   \
        const float4* fb = reinterpret_cast<const float4*>(                     \
            smem + FB0 + ((c) % 3) * CHUNK_BYTES);                              \
        uint32_t* ht = reinterpret_cast<uint32_t*>(                             \
            smem + HT0 + ((c) & 1) * HTSZ);                                     \
        _Pragma("unroll")                                                       \
        for (int j = 0; j < 4; ++j) {                                           \
            const int kp = krow0 + 4 * j;                                       \
            float4 A = fb[(2 * kp) * 64 + q64];                                 \
            float4 B = fb[(2 * kp + 1) * 64 + q64];                             \
            uint32_t p0 = pack_f16x2(B.x, A.x);                                 \
            uint32_t p1 = pack_f16x2(B.y, A.y);                                 \
            uint32_t p2 = pack_f16x2(B.z, A.z);                                 \
            uint32_t p3 = pack_f16x2(B.w, A.w);                                 \
            s4[0] += A.x + B.x;  s4[1] += A.y + B.y;                            \
            s4[2] += A.z + B.z;  s4[3] += A.w + B.w;                            \
            asm volatile("st.shared.v4.b32 [%0], {%1, %2, %3, %4};"             \
                :: "l"(&ht[kp * SROWW + dq4]),                                  \
                   "r"(p0), "r"(p1), "r"(p2), "r"(p3) : "memory");              \
        }                                                                       \
    } while (0)

    // ---- prologue: prefetch chunks 0..2, convert chunk 0 ----
    ISSUE_CHUNK(0); CP_COMMIT();
    ISSUE_CHUNK(1); CP_COMMIT();
    ISSUE_CHUNK(2); CP_COMMIT();
    CP_WAIT2();                      // this thread's chunk-0 copies complete
    CONVERT_CHUNK(0);
    __syncthreads();

#pragma unroll 1
    for (int c = 0; c < NCHUNK; ++c) {
        if (c + 3 < NCHUNK) ISSUE_CHUNK(c + 3);
        CP_COMMIT();                 // one group per iteration (may be empty)

        if (c + 1 < NCHUNK) {
            CP_WAIT2();              // this thread's chunk c+1 copies complete
            CONVERT_CHUNK(c + 1);    // writes ht[(c+1)&1]
        }

        const uint32_t* cur = reinterpret_cast<const uint32_t*>(
            smem + HT0 + (c & 1) * HTSZ);
        do_ks(cur, 0, mA64, cA, mB64, nb8, acc, g, tig);   // k 0..15
        do_ks(cur, 8, mA64, cA, mB64, nb8, acc, g, tig);   // k 16..31

        __syncthreads();
    }

    // ---- column-sum reduction ----
    psum[krow0 * 256 + dq4 + 0] = s4[0];
    psum[krow0 * 256 + dq4 + 1] = s4[1];
    psum[krow0 * 256 + dq4 + 2] = s4[2];
    psum[krow0 * 256 + dq4 + 3] = s4[3];
    __syncthreads();
    csum[tid] = psum[tid] + psum[256 + tid] + psum[512 + tid] + psum[768 + tid];
    __syncthreads();

    // ---- epilogue: cov = acc/N - mu_d mu_e, packed upper triangle ----
    const float invN = 1.0f / (float)NPTS;
    const size_t outb = (size_t)b * TRI;

#pragma unroll
    for (int u = 0; u < 5; ++u) {
        const int mb = (u < cA) ? mA64 : mB64;
#pragma unroll
        for (int mf = 0; mf < 4; ++mf) {
#pragma unroll
            for (int cc = 0; cc < 4; ++cc) {
                const int d = mb + mf * 16 + g + (cc >> 1) * 8;
                const int e = nb8[u] + 2 * tig + (cc & 1);
                if (e >= d) {
                    const float mu_d = csum[d] * invN;
                    const float mu_e = csum[e] * invN;
                    const int idx = d * DIM - (d * (d - 1)) / 2 - d + e;
                    out[outb + (size_t)idx] = acc[u][mf][cc] * invN - mu_d * mu_e;
                }
            }
        }
    }
}

extern "C" void kernel_launch(void* const* d_in, const int* in_sizes, int n_in,
                              void* d_out, int out_size)
{
    const float* X = (const float*)d_in[0];
    float* out = (float*)d_out;
    cudaFuncSetAttribute(cov_mma_kernel,
                         cudaFuncAttributeMaxDynamicSharedMemorySize,
                         SMEM_BYTES);
    cov_mma_kernel<<<BATCH * 2, 256, SMEM_BYTES>>>(X, out);
}